// round 4
// baseline (speedup 1.0000x reference)
#include <cuda_runtime.h>
#include <math.h>

#define NB 128
#define NT 512
#define NROWS 256      // B*S
#define BBS 128        // S
#define DD 128
#define FF 512
#define VV 1024
#define DK 32
#define LL 2

// ---------------- device scratch ----------------
__device__ float g_x[NROWS*DD];
__device__ float g_qkv[NROWS*384];
__device__ float g_att[NROWS*DD];
__device__ float g_ff[NROWS*FF];
__device__ float g_twqkv[LL][DD*384];
__device__ float g_two[LL][DD*DD];
__device__ float g_tw1[LL][DD*FF];
__device__ float g_tw2[LL][FF*DD];
__device__ float g_twout[DD*VV];
__device__ unsigned g_count;
__device__ unsigned g_gen;

struct Params {
    const int* tokens; const float* emb; const float* pos;
    const float* Wq; const float* bq; const float* Wk; const float* bk;
    const float* Wv; const float* bv; const float* Wo; const float* bo;
    const float* W1; const float* b1; const float* W2; const float* b2;
    const float* g1; const float* be1; const float* g2; const float* be2;
    const float* Wout; const float* bout;
    float* out;
};

// ---------------- l_mul elementwise transform ----------------
// e = floor(log2|x|)+1; f(x) = round(x*2^-e * 8) * 2^(2e-3);  lmul term == f(x)*f(w)
__device__ __forceinline__ float lmul_f(float x) {
    float ax = fabsf(x);
    if (ax == 0.0f) return 0.0f;
    int e = (int)floorf(log2f(ax)) + 1;
    if (e < -60 || e > 60) {
        float m = ldexpf(x, -e);
        float r = rintf(m * 8.0f);
        return ldexpf(r, 2*e - 3);
    }
    float m = x * __int_as_float((unsigned)(127 - e) << 23);
    float r = rintf(m * 8.0f);
    return r * __int_as_float((unsigned)((2*e - 3) + 127) << 23);
}

// ---------------- grid barrier ----------------
__device__ __forceinline__ void gbar() {
    __syncthreads();
    if (threadIdx.x == 0) {
        __threadfence();
        unsigned gen = *((volatile unsigned*)&g_gen);
        if (atomicAdd(&g_count, 1u) == NB - 1u) {
            atomicExch(&g_count, 0u);
            __threadfence();
            atomicExch(&g_gen, gen + 1u);
        } else {
            while (*((volatile unsigned*)&g_gen) == gen) __nanosleep(32);
        }
        __threadfence();
    }
    __syncthreads();
}

// ---------------- phase 0: weight transform + embed ----------------
__device__ void transform_all(const Params& P) {
    const int t0 = blockIdx.x * NT + threadIdx.x;
    const int STEP = NB * NT;
    for (int i = t0; i < LL*DD*384; i += STEP) {
        int l = i / (DD*384); int r = i - l*(DD*384);
        int k = r / 384, n = r - k*384;
        const float* src; int nn;
        if (n < 128)      { src = P.Wq + l*DD*DD; nn = n; }
        else if (n < 256) { src = P.Wk + l*DD*DD; nn = n - 128; }
        else              { src = P.Wv + l*DD*DD; nn = n - 256; }
        g_twqkv[l][k*384 + n] = lmul_f(src[nn*DD + k]);
    }
    for (int i = t0; i < LL*DD*DD; i += STEP) {
        int l = i / (DD*DD); int r = i - l*(DD*DD);
        int k = r >> 7, n = r & 127;
        g_two[l][k*DD + n] = lmul_f(P.Wo[l*DD*DD + n*DD + k]);
    }
    for (int i = t0; i < LL*DD*FF; i += STEP) {
        int l = i / (DD*FF); int r = i - l*(DD*FF);
        int k = r >> 9, n = r & 511;
        g_tw1[l][k*FF + n] = lmul_f(P.W1[l*FF*DD + n*DD + k]);
    }
    for (int i = t0; i < LL*FF*DD; i += STEP) {
        int l = i / (FF*DD); int r = i - l*(FF*DD);
        int k = r >> 7, n = r & 127;
        g_tw2[l][k*DD + n] = lmul_f(P.W2[l*DD*FF + n*FF + k]);
    }
    for (int i = t0; i < DD*VV; i += STEP) {
        int k = i >> 10, n = i & 1023;
        g_twout[k*VV + n] = lmul_f(P.Wout[n*DD + k]);
    }
    for (int i = t0; i < NROWS*DD; i += STEP) {
        int row = i >> 7, d = i & 127;
        int s = row & (BBS - 1);
        g_x[i] = P.emb[P.tokens[row]*DD + d] + P.pos[s*DD + d];
    }
}

// ---------------- GEMM: 8 rows x 128 cols, K=128, 512 threads --------------
// thread: c = tid&127 (col), q = tid>>7 (0..3) -> rows 2q, 2q+1
__device__ __forceinline__ void gemm8_128(
    const float* __restrict__ X, int ldx,
    const float* __restrict__ W, int N,
    const float* __restrict__ bias, bool relu,
    float* __restrict__ Y, int ldy,
    int row0, int col0, float* __restrict__ xs /* 8*132 */)
{
    const int tid = threadIdx.x;
    #pragma unroll
    for (int i = 0; i < 2; ++i) {
        int idx = tid + i*NT;              // 0..1023
        int r = idx >> 7, k = idx & 127;
        xs[r*132 + k] = lmul_f(X[(row0 + r)*ldx + k]);
    }
    __syncthreads();
    const int c = tid & 127;
    const int q = tid >> 7;
    const float* x0p = xs + (q*2    )*132;
    const float* x1p = xs + (q*2 + 1)*132;
    const float* wp = W + col0 + c;
    float a0 = 0.f, a1 = 0.f;
    #pragma unroll 8
    for (int k = 0; k < 128; k += 4) {
        float4 v0 = *(const float4*)(x0p + k);
        float4 v1 = *(const float4*)(x1p + k);
        float w0 = wp[(k+0)*N], w1 = wp[(k+1)*N], w2 = wp[(k+2)*N], w3 = wp[(k+3)*N];
        a0 = fmaf(v0.x, w0, a0); a1 = fmaf(v1.x, w0, a1);
        a0 = fmaf(v0.y, w1, a0); a1 = fmaf(v1.y, w1, a1);
        a0 = fmaf(v0.z, w2, a0); a1 = fmaf(v1.z, w2, a1);
        a0 = fmaf(v0.w, w3, a0); a1 = fmaf(v1.w, w3, a1);
    }
    float b = bias[c];
    a0 += b; a1 += b;
    if (relu) { a0 = fmaxf(a0, 0.f); a1 = fmaxf(a1, 0.f); }
    Y[(size_t)(row0 + q*2    )*ldy + col0 + c] = a0;
    Y[(size_t)(row0 + q*2 + 1)*ldy + col0 + c] = a1;
    __syncthreads();
}

// ---------------- GEMM: 16 rows x 128 cols, K=128 (final vocab proj) --------
__device__ __forceinline__ void gemm16_128(
    const float* __restrict__ X, int ldx,
    const float* __restrict__ W, int N,
    const float* __restrict__ bias,
    float* __restrict__ Y, int ldy,
    int row0, int col0, float* __restrict__ xs /* 16*132 */)
{
    const int tid = threadIdx.x;
    #pragma unroll
    for (int i = 0; i < 4; ++i) {
        int idx = tid + i*NT;              // 0..2047
        int r = idx >> 7, k = idx & 127;
        xs[r*132 + k] = lmul_f(X[(row0 + r)*ldx + k]);
    }
    __syncthreads();
    const int c = tid & 127;
    const int q = tid >> 7;                // rows 4q..4q+3
    const float* x0p = xs + (q*4    )*132;
    const float* x1p = xs + (q*4 + 1)*132;
    const float* x2p = xs + (q*4 + 2)*132;
    const float* x3p = xs + (q*4 + 3)*132;
    const float* wp = W + col0 + c;
    float a0 = 0.f, a1 = 0.f, a2 = 0.f, a3 = 0.f;
    #pragma unroll 4
    for (int k = 0; k < 128; k += 4) {
        float4 v0 = *(const float4*)(x0p + k);
        float4 v1 = *(const float4*)(x1p + k);
        float4 v2 = *(const float4*)(x2p + k);
        float4 v3 = *(const float4*)(x3p + k);
        float w0 = wp[(k+0)*N], w1 = wp[(k+1)*N], w2 = wp[(k+2)*N], w3 = wp[(k+3)*N];
        a0 = fmaf(v0.x, w0, a0); a1 = fmaf(v1.x, w0, a1); a2 = fmaf(v2.x, w0, a2); a3 = fmaf(v3.x, w0, a3);
        a0 = fmaf(v0.y, w1, a0); a1 = fmaf(v1.y, w1, a1); a2 = fmaf(v2.y, w1, a2); a3 = fmaf(v3.y, w1, a3);
        a0 = fmaf(v0.z, w2, a0); a1 = fmaf(v1.z, w2, a1); a2 = fmaf(v2.z, w2, a2); a3 = fmaf(v3.z, w2, a3);
        a0 = fmaf(v0.w, w3, a0); a1 = fmaf(v1.w, w3, a1); a2 = fmaf(v2.w, w3, a2); a3 = fmaf(v3.w, w3, a3);
    }
    float b = bias[c];
    Y[(size_t)(row0 + q*4    )*ldy + col0 + c] = a0 + b;
    Y[(size_t)(row0 + q*4 + 1)*ldy + col0 + c] = a1 + b;
    Y[(size_t)(row0 + q*4 + 2)*ldy + col0 + c] = a2 + b;
    Y[(size_t)(row0 + q*4 + 3)*ldy + col0 + c] = a3 + b;
    __syncthreads();
}

// ---------------- attention tile: (b, h, 16-query block); warp per query ------
__device__ __forceinline__ void attn_tile(
    const float* __restrict__ qkv, float* __restrict__ attout,
    int b, int h, int qt, float* __restrict__ sm)
{
    float* ksh = sm;               // 128*33 = 4224
    float* vsh = sm + 4224;        // 128*33
    float* qsh = sm + 8448;        // 16*32 = 512
    float* psh = sm + 8960;        // 16*128 = 2048
    const int tid = threadIdx.x;
    #pragma unroll
    for (int i = 0; i < 8; ++i) {
        int idx = tid + i*NT;       // 0..4095
        int j = idx >> 5, d = idx & 31;
        const float* base = qkv + (size_t)(b*BBS + j)*384 + h*DK + d;
        ksh[j*33 + d] = base[128];
        vsh[j*33 + d] = base[256];
    }
    {
        int qi = tid >> 5, d = tid & 31;   // 16*32 = 512 = NT
        qsh[tid] = qkv[(size_t)(b*BBS + qt*16 + qi)*384 + h*DK + d];
    }
    __syncthreads();
    const int wid = tid >> 5, lane = tid & 31;
    const int q = qt*16 + wid;
    float qr[32];
    #pragma unroll
    for (int d = 0; d < 32; d += 4) {
        float4 t = *(const float4*)(qsh + wid*32 + d);
        qr[d] = t.x; qr[d+1] = t.y; qr[d+2] = t.z; qr[d+3] = t.w;
    }
    const float* k0 = ksh + (lane     )*33;
    const float* k1 = ksh + (lane + 32)*33;
    const float* k2 = ksh + (lane + 64)*33;
    const float* k3 = ksh + (lane + 96)*33;
    float s0 = 0.f, s1 = 0.f, s2 = 0.f, s3 = 0.f;
    #pragma unroll
    for (int d = 0; d < 32; ++d) {
        float qd = qr[d];
        s0 = fmaf(qd, k0[d], s0);
        s1 = fmaf(qd, k1[d], s1);
        s2 = fmaf(qd, k2[d], s2);
        s3 = fmaf(qd, k3[d], s3);
    }
    const float scale = 0.17677669529663687f;  // 1/sqrt(32)
    s0 *= scale; s1 *= scale; s2 *= scale; s3 *= scale;
    float m = fmaxf(fmaxf(s0, s1), fmaxf(s2, s3));
    #pragma unroll
    for (int o = 16; o; o >>= 1) m = fmaxf(m, __shfl_xor_sync(0xffffffffu, m, o));
    float p0 = __expf(s0 - m), p1 = __expf(s1 - m), p2 = __expf(s2 - m), p3 = __expf(s3 - m);
    float lsum = p0 + p1 + p2 + p3;
    #pragma unroll
    for (int o = 16; o; o >>= 1) lsum += __shfl_xor_sync(0xffffffffu, lsum, o);
    float* pp = psh + wid*128;
    pp[lane     ] = p0;
    pp[lane + 32] = p1;
    pp[lane + 64] = p2;
    pp[lane + 96] = p3;
    __syncwarp();
    float o0 = 0.f, o1 = 0.f, o2 = 0.f, o3 = 0.f;
    #pragma unroll 8
    for (int j = 0; j < 128; j += 4) {
        o0 = fmaf(pp[j+0], vsh[(j+0)*33 + lane], o0);
        o1 = fmaf(pp[j+1], vsh[(j+1)*33 + lane], o1);
        o2 = fmaf(pp[j+2], vsh[(j+2)*33 + lane], o2);
        o3 = fmaf(pp[j+3], vsh[(j+3)*33 + lane], o3);
    }
    attout[(size_t)(b*BBS + q)*DD + h*DK + lane] = ((o0 + o1) + (o2 + o3)) / lsum;
    __syncthreads();
}

// ---------------- shared LN epilogue over 8 rows staged in vals[8*132] --------
// v = value this thread owns for (local rows 2q,2q+1, col c); writes x.
__device__ __forceinline__ void ln8_epilogue(
    float v0, float v1, int row0, int c, int q,
    const float* __restrict__ g, const float* __restrict__ be,
    float* __restrict__ x, float* __restrict__ vals, float* __restrict__ st)
{
    vals[(q*2    )*132 + c] = v0;
    vals[(q*2 + 1)*132 + c] = v1;
    __syncthreads();
    const int wid = threadIdx.x >> 5, lane = threadIdx.x & 31;
    if (wid < 8) {
        float s = 0.f, sq = 0.f;
        #pragma unroll
        for (int i = 0; i < 4; ++i) {
            float t = vals[wid*132 + lane + i*32];
            s += t; sq = fmaf(t, t, sq);
        }
        #pragma unroll
        for (int o = 16; o; o >>= 1) {
            s  += __shfl_xor_sync(0xffffffffu, s, o);
            sq += __shfl_xor_sync(0xffffffffu, sq, o);
        }
        if (lane == 0) {
            float mean = s * (1.f/128.f);
            float var  = sq * (1.f/128.f) - mean*mean;
            st[wid*2]     = mean;
            st[wid*2 + 1] = rsqrtf(var + 1e-5f);
        }
    }
    __syncthreads();
    float gm = g[c], bb = be[c];
    x[(row0 + q*2    )*DD + c] = (v0 - st[(q*2  )*2])*st[(q*2  )*2 + 1]*gm + bb;
    x[(row0 + q*2 + 1)*DD + c] = (v1 - st[(q*2+1)*2])*st[(q*2+1)*2 + 1]*gm + bb;
    __syncthreads();
}

// ---------------- O-proj + residual + LN1: 8 rows/block, 32 blocks ----------
__device__ __forceinline__ void oproj_ln(
    const float* __restrict__ att, const float* __restrict__ W,
    const float* __restrict__ bo, const float* __restrict__ g1,
    const float* __restrict__ be1, float* __restrict__ x,
    float* __restrict__ sm)
{
    if (blockIdx.x >= 32) return;
    const int row0 = blockIdx.x * 8;
    float* xs   = sm;           // 8*132 = 1056
    float* vals = sm + 1056;    // 8*132
    float* st   = sm + 2112;    // 16
    const int tid = threadIdx.x;
    #pragma unroll
    for (int i = 0; i < 2; ++i) {
        int idx = tid + i*NT;
        int r = idx >> 7, k = idx & 127;
        xs[r*132 + k] = lmul_f(att[(row0 + r)*DD + k]);
    }
    __syncthreads();
    const int c = tid & 127, q = tid >> 7;
    const float* x0p = xs + (q*2    )*132;
    const float* x1p = xs + (q*2 + 1)*132;
    const float* wp = W + c;
    float a0 = 0.f, a1 = 0.f;
    #pragma unroll 8
    for (int k = 0; k < 128; k += 4) {
        float4 v0 = *(const float4*)(x0p + k);
        float4 v1 = *(const float4*)(x1p + k);
        float w0 = wp[(k+0)*DD], w1 = wp[(k+1)*DD], w2 = wp[(k+2)*DD], w3 = wp[(k+3)*DD];
        a0 = fmaf(v0.x, w0, a0); a1 = fmaf(v1.x, w0, a1);
        a0 = fmaf(v0.y, w1, a0); a1 = fmaf(v1.y, w1, a1);
        a0 = fmaf(v0.z, w2, a0); a1 = fmaf(v1.z, w2, a1);
        a0 = fmaf(v0.w, w3, a0); a1 = fmaf(v1.w, w3, a1);
    }
    float b = bo[c];
    float v0 = x[(row0 + q*2    )*DD + c] + a0 + b;
    float v1 = x[(row0 + q*2 + 1)*DD + c] + a1 + b;
    ln8_epilogue(v0, v1, row0, c, q, g1, be1, x, vals, st);
}

// ---------------- FF2 (K=512) + bias + residual + LN2: 8 rows, 32 blocks ------
__device__ __forceinline__ void ff2_ln(
    const float* __restrict__ ff, const float* __restrict__ W,
    const float* __restrict__ b2, const float* __restrict__ g2,
    const float* __restrict__ be2, float* __restrict__ x,
    float* __restrict__ sm)
{
    if (blockIdx.x >= 32) return;
    const int row0 = blockIdx.x * 8;
    float* xs   = sm;            // 8*516 = 4128
    float* vals = sm + 4128;     // 8*132
    float* st   = sm + 5184;     // 16
    const int tid = threadIdx.x;
    #pragma unroll
    for (int i = 0; i < 8; ++i) {
        int idx = tid + i*NT;     // 0..4095
        int r = idx >> 9, k = idx & 511;
        xs[r*516 + k] = lmul_f(ff[(row0 + r)*FF + k]);
    }
    __syncthreads();
    const int c = tid & 127, q = tid >> 7;
    const float* x0p = xs + (q*2    )*516;
    const float* x1p = xs + (q*2 + 1)*516;
    const float* wp = W + c;
    float a0 = 0.f, a1 = 0.f;
    #pragma unroll 8
    for (int k = 0; k < 512; k += 4) {
        float4 v0 = *(const float4*)(x0p + k);
        float4 v1 = *(const float4*)(x1p + k);
        float w0 = wp[(k+0)*DD], w1 = wp[(k+1)*DD], w2 = wp[(k+2)*DD], w3 = wp[(k+3)*DD];
        a0 = fmaf(v0.x, w0, a0); a1 = fmaf(v1.x, w0, a1);
        a0 = fmaf(v0.y, w1, a0); a1 = fmaf(v1.y, w1, a1);
        a0 = fmaf(v0.z, w2, a0); a1 = fmaf(v1.z, w2, a1);
        a0 = fmaf(v0.w, w3, a0); a1 = fmaf(v1.w, w3, a1);
    }
    float b = b2[c];
    float v0 = x[(row0 + q*2    )*DD + c] + a0 + b;
    float v1 = x[(row0 + q*2 + 1)*DD + c] + a1 + b;
    ln8_epilogue(v0, v1, row0, c, q, g2, be2, x, vals, st);
}

// ---------------- the one persistent kernel ----------------
__global__ void __launch_bounds__(NT, 1) model_kernel(Params P) {
    __shared__ __align__(16) float sm[11008];

    // P0: weight transforms + embedding
    transform_all(P);
    gbar();

    for (int l = 0; l < LL; ++l) {
        // P1: QKV fused GEMM — 96 tiles (32 row x 3 col)
        if (blockIdx.x < 96) {
            int rt = blockIdx.x & 31, ct = blockIdx.x >> 5;
            const float* segb = (ct == 0 ? P.bq : ct == 1 ? P.bk : P.bv) + l*DD;
            gemm8_128(g_x, DD, g_twqkv[l], 384, segb, false,
                      g_qkv, 384, rt*8, ct*128, sm);
        }
        gbar();

        // P2: attention — 64 tiles (b, h, 16-query block)
        if (blockIdx.x < 64) {
            int b = blockIdx.x >> 5, h = (blockIdx.x >> 3) & 3, qt = blockIdx.x & 7;
            attn_tile(g_qkv, g_att, b, h, qt, sm);
        }
        gbar();

        // P3: O-proj + residual + LN1 — 32 blocks
        oproj_ln(g_att, g_two[l], P.bo + l*DD, P.g1 + l*DD, P.be1 + l*DD, g_x, sm);
        gbar();

        // P4: FF1 + relu — 128 tiles (32 row x 4 col)
        {
            int rt = blockIdx.x & 31, ct = blockIdx.x >> 5;
            gemm8_128(g_x, DD, g_tw1[l], FF, P.b1 + l*FF + ct*128, true,
                      g_ff, FF, rt*8, ct*128, sm);
        }
        gbar();

        // P5: FF2 + bias + residual + LN2 — 32 blocks (K=512 fused)
        ff2_ln(g_ff, g_tw2[l], P.b2 + l*DD, P.g2 + l*DD, P.be2 + l*DD, g_x, sm);
        gbar();
    }

    // P6: final vocab projection — 128 tiles (16 row-tiles x 8 col-tiles)
    {
        int rt = blockIdx.x & 15, ct = blockIdx.x >> 4;
        gemm16_128(g_x, DD, g_twout, VV, P.bout + ct*128,
                   P.out, VV, rt*16, ct*128, sm);
    }
}

extern "C" void kernel_launch(void* const* d_in, const int* in_sizes, int n_in,
                              void* d_out, int out_size) {
    Params P;
    P.tokens = (const int*)  d_in[0];
    P.emb    = (const float*)d_in[1];
    P.pos    = (const float*)d_in[2];
    P.Wq     = (const float*)d_in[3];
    P.bq     = (const float*)d_in[4];
    P.Wk     = (const float*)d_in[5];
    P.bk     = (const float*)d_in[6];
    P.Wv     = (const float*)d_in[7];
    P.bv     = (const float*)d_in[8];
    P.Wo     = (const float*)d_in[9];
    P.bo     = (const float*)d_in[10];
    P.W1     = (const float*)d_in[11];
    P.b1     = (const float*)d_in[12];
    P.W2     = (const float*)d_in[13];
    P.b2     = (const float*)d_in[14];
    P.g1     = (const float*)d_in[15];
    P.be1    = (const float*)d_in[16];
    P.g2     = (const float*)d_in[17];
    P.be2    = (const float*)d_in[18];
    P.Wout   = (const float*)d_in[19];
    P.bout   = (const float*)d_in[20];
    P.out    = (float*)d_out;

    model_kernel<<<NB, NT>>>(P);
}

// round 5
// speedup vs baseline: 1.1894x; 1.1894x over previous
#include <cuda_runtime.h>
#include <math.h>

#define NB 148
#define NT 256
#define NROWS 256      // B*S
#define BBS 128        // S
#define DD 128
#define FF 512
#define VV 1024
#define DK 32
#define LL 2

// ---------------- device scratch ----------------
__device__ float g_x[NROWS*DD];
__device__ float g_qkv[NROWS*384];
__device__ float g_att[NROWS*DD];
__device__ float g_ff[NROWS*FF];
__device__ float g_ffp[4][NROWS*DD];
__device__ float g_twqkv[LL][DD*384];
__device__ float g_two[LL][DD*DD];
__device__ float g_tw1[LL][DD*FF];
__device__ float g_tw2[LL][FF*DD];
__device__ float g_twout[DD*VV];
__device__ unsigned g_count;
__device__ unsigned g_gen;

struct Params {
    const int* tokens; const float* emb; const float* pos;
    const float* Wq; const float* bq; const float* Wk; const float* bk;
    const float* Wv; const float* bv; const float* Wo; const float* bo;
    const float* W1; const float* b1; const float* W2; const float* b2;
    const float* g1; const float* be1; const float* g2; const float* be2;
    const float* Wout; const float* bout;
    float* out;
};

// ---------------- l_mul elementwise transform ----------------
// e = floor(log2|x|)+1; f(x) = round(x*2^-e * 8) * 2^(2e-3); lmul term == f(x)*f(w)
__device__ __forceinline__ float lmul_f(float x) {
    float ax = fabsf(x);
    if (ax == 0.0f) return 0.0f;
    int e = (int)floorf(log2f(ax)) + 1;
    if (e < -60 || e > 60) {
        float m = ldexpf(x, -e);
        float r = rintf(m * 8.0f);
        return ldexpf(r, 2*e - 3);
    }
    float m = x * __int_as_float((unsigned)(127 - e) << 23);
    float r = rintf(m * 8.0f);
    return r * __int_as_float((unsigned)((2*e - 3) + 127) << 23);
}

// ---------------- grid barrier (tight spin) ----------------
__device__ __noinline__ void gbar() {
    __syncthreads();
    if (threadIdx.x == 0) {
        __threadfence();
        unsigned gen = *((volatile unsigned*)&g_gen);
        if (atomicAdd(&g_count, 1u) == NB - 1u) {
            atomicExch(&g_count, 0u);
            __threadfence();
            atomicExch(&g_gen, gen + 1u);
        } else {
            while (*((volatile unsigned*)&g_gen) == gen) { }
        }
        __threadfence();
    }
    __syncthreads();
}

// ---------------- phase 0: weight transform + embed ----------------
__device__ __noinline__ void transform_all(const Params* __restrict__ P) {
    const int t0 = blockIdx.x * NT + threadIdx.x;
    const int STEP = NB * NT;
    for (int i = t0; i < LL*DD*384; i += STEP) {
        int l = i / (DD*384); int r = i - l*(DD*384);
        int k = r / 384, n = r - k*384;
        const float* src; int nn;
        if (n < 128)      { src = P->Wq + l*DD*DD; nn = n; }
        else if (n < 256) { src = P->Wk + l*DD*DD; nn = n - 128; }
        else              { src = P->Wv + l*DD*DD; nn = n - 256; }
        g_twqkv[l][k*384 + n] = lmul_f(src[nn*DD + k]);
    }
    for (int i = t0; i < LL*DD*DD; i += STEP) {
        int l = i / (DD*DD); int r = i - l*(DD*DD);
        int k = r >> 7, n = r & 127;
        g_two[l][k*DD + n] = lmul_f(P->Wo[l*DD*DD + n*DD + k]);
    }
    for (int i = t0; i < LL*DD*FF; i += STEP) {
        int l = i / (DD*FF); int r = i - l*(DD*FF);
        int k = r >> 9, n = r & 511;
        g_tw1[l][k*FF + n] = lmul_f(P->W1[l*FF*DD + n*DD + k]);
    }
    for (int i = t0; i < LL*FF*DD; i += STEP) {
        int l = i / (FF*DD); int r = i - l*(FF*DD);
        int k = r >> 7, n = r & 127;
        g_tw2[l][k*DD + n] = lmul_f(P->W2[l*DD*FF + n*FF + k]);
    }
    for (int i = t0; i < DD*VV; i += STEP) {
        int k = i >> 10, n = i & 1023;
        g_twout[k*VV + n] = lmul_f(P->Wout[n*DD + k]);
    }
    for (int i = t0; i < NROWS*DD; i += STEP) {
        int row = i >> 7, d = i & 127;
        int s = row & (BBS - 1);
        g_x[i] = P->emb[P->tokens[row]*DD + d] + P->pos[s*DD + d];
    }
}

// ---------------- generic GEMM tile: 8 rows x 128 cols, K-chunk = 128 --------
// ONE code copy (noinline) shared by QKV / FF1 / FF2-partials / vocab.
__device__ __noinline__ void gemm_tile(
    const float* __restrict__ X, int ldx, int kbeg,
    const float* __restrict__ W, int N,
    const float* __restrict__ bias,    // indexed [c]; may be null
    int relu,
    float* __restrict__ Y, int ldy,
    int row0, int col0, float* __restrict__ xs /* 8*132 */)
{
    const int tid = threadIdx.x;
    #pragma unroll
    for (int i = 0; i < 4; ++i) {
        int idx = tid + i*NT;              // 0..1023
        int r = idx >> 7, k = idx & 127;
        xs[r*132 + k] = lmul_f(X[(row0 + r)*ldx + kbeg + k]);
    }
    __syncthreads();
    const int c = tid & 127;
    const int rg = (tid >> 7) << 2;        // 0 or 4
    const float* wp = W + (size_t)kbeg * N + col0 + c;
    const float* x0p = xs + (rg+0)*132;
    const float* x1p = xs + (rg+1)*132;
    const float* x2p = xs + (rg+2)*132;
    const float* x3p = xs + (rg+3)*132;
    float a0 = 0.f, a1 = 0.f, a2 = 0.f, a3 = 0.f;
    #pragma unroll 8
    for (int k = 0; k < 128; k += 4) {
        float4 v0 = *(const float4*)(x0p + k);
        float4 v1 = *(const float4*)(x1p + k);
        float4 v2 = *(const float4*)(x2p + k);
        float4 v3 = *(const float4*)(x3p + k);
        float w0 = wp[(size_t)(k+0)*N];
        float w1 = wp[(size_t)(k+1)*N];
        float w2 = wp[(size_t)(k+2)*N];
        float w3 = wp[(size_t)(k+3)*N];
        a0 = fmaf(v0.x, w0, a0); a1 = fmaf(v1.x, w0, a1); a2 = fmaf(v2.x, w0, a2); a3 = fmaf(v3.x, w0, a3);
        a0 = fmaf(v0.y, w1, a0); a1 = fmaf(v1.y, w1, a1); a2 = fmaf(v2.y, w1, a2); a3 = fmaf(v3.y, w1, a3);
        a0 = fmaf(v0.z, w2, a0); a1 = fmaf(v1.z, w2, a1); a2 = fmaf(v2.z, w2, a2); a3 = fmaf(v3.z, w2, a3);
        a0 = fmaf(v0.w, w3, a0); a1 = fmaf(v1.w, w3, a1); a2 = fmaf(v2.w, w3, a2); a3 = fmaf(v3.w, w3, a3);
    }
    float b = bias ? bias[c] : 0.f;
    a0 += b; a1 += b; a2 += b; a3 += b;
    if (relu) {
        a0 = fmaxf(a0, 0.f); a1 = fmaxf(a1, 0.f);
        a2 = fmaxf(a2, 0.f); a3 = fmaxf(a3, 0.f);
    }
    Y[(size_t)(row0+rg+0)*ldy + col0 + c] = a0;
    Y[(size_t)(row0+rg+1)*ldy + col0 + c] = a1;
    Y[(size_t)(row0+rg+2)*ldy + col0 + c] = a2;
    Y[(size_t)(row0+rg+3)*ldy + col0 + c] = a3;
    __syncthreads();
}

// ---------------- attention tile: (b, h, 8-query block); warp per query -------
__device__ __noinline__ void attn_tile(
    const float* __restrict__ qkv, float* __restrict__ attout,
    int b, int h, int qb, float* __restrict__ sm)
{
    float* ksh = sm;               // 128*33
    float* vsh = sm + 4224;        // 128*33
    float* qsh = sm + 8448;        // 8*32
    float* psh = sm + 8704;        // 8*128
    const int tid = threadIdx.x;
    #pragma unroll
    for (int i = 0; i < 16; ++i) {
        int idx = tid + i*NT;       // 0..4095
        int j = idx >> 5, d = idx & 31;
        const float* base = qkv + (size_t)(b*BBS + j)*384 + h*DK + d;
        ksh[j*33 + d] = base[128];
        vsh[j*33 + d] = base[256];
    }
    {
        int qi = tid >> 5, d = tid & 31;   // 8*32 = 256 = NT
        qsh[tid] = qkv[(size_t)(b*BBS + qb*8 + qi)*384 + h*DK + d];
    }
    __syncthreads();
    const int wid = tid >> 5, lane = tid & 31;
    const int q = qb*8 + wid;
    float qr[32];
    #pragma unroll
    for (int d = 0; d < 32; d += 4) {
        float4 t = *(const float4*)(qsh + wid*32 + d);
        qr[d] = t.x; qr[d+1] = t.y; qr[d+2] = t.z; qr[d+3] = t.w;
    }
    const float* k0 = ksh + (lane     )*33;
    const float* k1 = ksh + (lane + 32)*33;
    const float* k2 = ksh + (lane + 64)*33;
    const float* k3 = ksh + (lane + 96)*33;
    float s0 = 0.f, s1 = 0.f, s2 = 0.f, s3 = 0.f;
    #pragma unroll
    for (int d = 0; d < 32; ++d) {
        float qd = qr[d];
        s0 = fmaf(qd, k0[d], s0);
        s1 = fmaf(qd, k1[d], s1);
        s2 = fmaf(qd, k2[d], s2);
        s3 = fmaf(qd, k3[d], s3);
    }
    const float scale = 0.17677669529663687f;  // 1/sqrt(32)
    s0 *= scale; s1 *= scale; s2 *= scale; s3 *= scale;
    float m = fmaxf(fmaxf(s0, s1), fmaxf(s2, s3));
    #pragma unroll
    for (int o = 16; o; o >>= 1) m = fmaxf(m, __shfl_xor_sync(0xffffffffu, m, o));
    float p0 = __expf(s0 - m), p1 = __expf(s1 - m), p2 = __expf(s2 - m), p3 = __expf(s3 - m);
    float lsum = p0 + p1 + p2 + p3;
    #pragma unroll
    for (int o = 16; o; o >>= 1) lsum += __shfl_xor_sync(0xffffffffu, lsum, o);
    float* pp = psh + wid*128;
    pp[lane     ] = p0;
    pp[lane + 32] = p1;
    pp[lane + 64] = p2;
    pp[lane + 96] = p3;
    __syncwarp();
    float o0 = 0.f, o1 = 0.f, o2 = 0.f, o3 = 0.f;
    #pragma unroll 8
    for (int j = 0; j < 128; j += 4) {
        o0 = fmaf(pp[j+0], vsh[(j+0)*33 + lane], o0);
        o1 = fmaf(pp[j+1], vsh[(j+1)*33 + lane], o1);
        o2 = fmaf(pp[j+2], vsh[(j+2)*33 + lane], o2);
        o3 = fmaf(pp[j+3], vsh[(j+3)*33 + lane], o3);
    }
    attout[(size_t)(b*BBS + q)*DD + h*DK + lane] = ((o0 + o1) + (o2 + o3)) / lsum;
    __syncthreads();
}

// ---------------- O-proj + residual + LN1 (4 rows/block, 64 blocks) ----------
__device__ __noinline__ void oproj_ln(
    const float* __restrict__ att, const float* __restrict__ W,
    const float* __restrict__ bo, const float* __restrict__ g1,
    const float* __restrict__ be1, float* __restrict__ x,
    float* __restrict__ sm)
{
    if (blockIdx.x >= 64) return;
    const int row0 = blockIdx.x * 4;
    float* as   = sm;          // 4*132
    float* vals = sm + 544;    // 4*132
    float* st   = sm + 1088;   // 8
    const int tid = threadIdx.x;
    #pragma unroll
    for (int i = 0; i < 2; ++i) {
        int idx = tid + i*NT;          // 0..511
        int r = idx >> 7, k = idx & 127;
        as[r*132 + k] = lmul_f(att[(row0 + r)*DD + k]);
    }
    __syncthreads();
    const int c = tid & 127, rg = tid >> 7;       // rows rg*2, rg*2+1
    const float* x0p = as + (rg*2    )*132;
    const float* x1p = as + (rg*2 + 1)*132;
    const float* wp = W + c;
    float a0 = 0.f, a1 = 0.f;
    #pragma unroll 8
    for (int k = 0; k < 128; k += 4) {
        float4 v0 = *(const float4*)(x0p + k);
        float4 v1 = *(const float4*)(x1p + k);
        float w0 = wp[(k+0)*DD], w1 = wp[(k+1)*DD], w2 = wp[(k+2)*DD], w3 = wp[(k+3)*DD];
        a0 = fmaf(v0.x, w0, a0); a1 = fmaf(v1.x, w0, a1);
        a0 = fmaf(v0.y, w1, a0); a1 = fmaf(v1.y, w1, a1);
        a0 = fmaf(v0.z, w2, a0); a1 = fmaf(v1.z, w2, a1);
        a0 = fmaf(v0.w, w3, a0); a1 = fmaf(v1.w, w3, a1);
    }
    float b = bo[c];
    const int r0 = row0 + rg*2, r1 = r0 + 1;
    float v0 = x[r0*DD + c] + a0 + b;
    float v1 = x[r1*DD + c] + a1 + b;
    vals[(rg*2    )*132 + c] = v0;
    vals[(rg*2 + 1)*132 + c] = v1;
    __syncthreads();
    const int wid = tid >> 5, lane = tid & 31;
    if (wid < 4) {
        float s = 0.f, sq = 0.f;
        #pragma unroll
        for (int i = 0; i < 4; ++i) {
            float v = vals[wid*132 + lane + i*32];
            s += v; sq = fmaf(v, v, sq);
        }
        #pragma unroll
        for (int o = 16; o; o >>= 1) {
            s  += __shfl_xor_sync(0xffffffffu, s, o);
            sq += __shfl_xor_sync(0xffffffffu, sq, o);
        }
        if (lane == 0) {
            float mean = s * (1.f/128.f);
            float var  = sq * (1.f/128.f) - mean*mean;
            st[wid*2]     = mean;
            st[wid*2 + 1] = rsqrtf(var + 1e-5f);
        }
    }
    __syncthreads();
    {
        float gm = g1[c], bb = be1[c];
        float m0 = st[(rg*2)*2],     rs0 = st[(rg*2)*2 + 1];
        float m1 = st[(rg*2+1)*2],   rs1 = st[(rg*2+1)*2 + 1];
        x[r0*DD + c] = (v0 - m0)*rs0*gm + bb;
        x[r1*DD + c] = (v1 - m1)*rs1*gm + bb;
    }
    __syncthreads();
}

// ---------------- FF2 partial combine + bias + residual + LN2 -----------------
__device__ __noinline__ void ff2_ln(
    const float* __restrict__ b2, const float* __restrict__ g2,
    const float* __restrict__ be2, float* __restrict__ x,
    float* __restrict__ sm)
{
    if (blockIdx.x >= 128) return;
    float* vals = sm;         // 2*132
    float* st   = sm + 272;   // 4
    const int tid = threadIdx.x;
    const int c = tid & 127, rg = tid >> 7;
    const int row = blockIdx.x*2 + rg;
    float v = x[row*DD + c] + b2[c];
    #pragma unroll
    for (int ks = 0; ks < 4; ++ks) v += g_ffp[ks][row*DD + c];
    vals[rg*132 + c] = v;
    __syncthreads();
    const int wid = tid >> 5, lane = tid & 31;
    if (wid < 2) {
        float s = 0.f, sq = 0.f;
        #pragma unroll
        for (int i = 0; i < 4; ++i) {
            float t = vals[wid*132 + lane + i*32];
            s += t; sq = fmaf(t, t, sq);
        }
        #pragma unroll
        for (int o = 16; o; o >>= 1) {
            s  += __shfl_xor_sync(0xffffffffu, s, o);
            sq += __shfl_xor_sync(0xffffffffu, sq, o);
        }
        if (lane == 0) {
            float mean = s * (1.f/128.f);
            float var  = sq * (1.f/128.f) - mean*mean;
            st[wid*2]     = mean;
            st[wid*2 + 1] = rsqrtf(var + 1e-5f);
        }
    }
    __syncthreads();
    x[row*DD + c] = (v - st[rg*2])*st[rg*2 + 1]*g2[c] + be2[c];
    __syncthreads();
}

// ---------------- the one persistent kernel ----------------
__global__ void __launch_bounds__(NT, 1) model_kernel(Params P) {
    __shared__ __align__(16) float sm[9760];

    // P0: weight transforms + embedding
    transform_all(&P);
    gbar();

    for (int l = 0; l < LL; ++l) {
        // P1: QKV fused GEMM — 96 tiles (32 row x 3 col)
        if (blockIdx.x < 96) {
            int rt = blockIdx.x & 31, ct = blockIdx.x >> 5;
            const float* segb = (ct == 0 ? P.bq : ct == 1 ? P.bk : P.bv) + l*DD;
            gemm_tile(g_x, DD, 0, g_twqkv[l], 384, segb, 0,
                      g_qkv, 384, rt*8, ct*128, sm);
        }
        gbar();

        // P2: attention — 128 tiles (b, h, qb)
        if (blockIdx.x < 128) {
            int b = blockIdx.x >> 6, h = (blockIdx.x >> 4) & 3, qb = blockIdx.x & 15;
            attn_tile(g_qkv, g_att, b, h, qb, sm);
        }
        gbar();

        // P3: O-proj + residual + LN1 — 64 blocks
        oproj_ln(g_att, g_two[l], P.bo + l*DD, P.g1 + l*DD, P.be1 + l*DD, g_x, sm);
        gbar();

        // P4: FF1 + relu — 128 tiles (32 row x 4 col)
        if (blockIdx.x < 128) {
            int rt = blockIdx.x & 31, ct = blockIdx.x >> 5;
            gemm_tile(g_x, DD, 0, g_tw1[l], FF, P.b1 + l*FF + ct*128, 1,
                      g_ff, FF, rt*8, ct*128, sm);
        }
        gbar();

        // P5: FF2 k-split partials — 128 tiles (32 row-tiles x 4 k-chunks)
        if (blockIdx.x < 128) {
            int rt = blockIdx.x & 31, ks = blockIdx.x >> 5;
            gemm_tile(g_ff, FF, ks*128, g_tw2[l], DD, (const float*)0, 0,
                      g_ffp[ks], DD, rt*8, 0, sm);
        }
        gbar();

        // P6: partial sum + bias + residual + LN2 — 128 blocks
        ff2_ln(P.b2 + l*DD, P.g2 + l*DD, P.be2 + l*DD, g_x, sm);
        gbar();
    }

    // P7: final vocab projection — 256 tiles strided over 148 blocks
    for (int t = blockIdx.x; t < 256; t += NB) {
        int rt = t & 31, ct = t >> 5;
        gemm_tile(g_x, DD, 0, g_twout, VV, P.bout + ct*128, 0,
                  P.out, VV, rt*8, ct*128, sm);
    }
}

extern "C" void kernel_launch(void* const* d_in, const int* in_sizes, int n_in,
                              void* d_out, int out_size) {
    Params P;
    P.tokens = (const int*)  d_in[0];
    P.emb    = (const float*)d_in[1];
    P.pos    = (const float*)d_in[2];
    P.Wq     = (const float*)d_in[3];
    P.bq     = (const float*)d_in[4];
    P.Wk     = (const float*)d_in[5];
    P.bk     = (const float*)d_in[6];
    P.Wv     = (const float*)d_in[7];
    P.bv     = (const float*)d_in[8];
    P.Wo     = (const float*)d_in[9];
    P.bo     = (const float*)d_in[10];
    P.W1     = (const float*)d_in[11];
    P.b1     = (const float*)d_in[12];
    P.W2     = (const float*)d_in[13];
    P.b2     = (const float*)d_in[14];
    P.g1     = (const float*)d_in[15];
    P.be1    = (const float*)d_in[16];
    P.g2     = (const float*)d_in[17];
    P.be2    = (const float*)d_in[18];
    P.Wout   = (const float*)d_in[19];
    P.bout   = (const float*)d_in[20];
    P.out    = (float*)d_out;

    model_kernel<<<NB, NT>>>(P);
}

// round 6
// speedup vs baseline: 1.2860x; 1.0812x over previous
#include <cuda_runtime.h>
#include <math.h>

#define NB 296
#define NT 256
#define NROWS 256      // B*S
#define BBS 128        // S
#define DD 128
#define FF 512
#define VV 1024
#define DK 32
#define LL 2

// ---------------- device scratch ----------------
__device__ float g_x[NROWS*DD];
__device__ float g_qkv[NROWS*384];
__device__ float g_att[NROWS*DD];
__device__ float g_ff[NROWS*FF];
__device__ float g_ffp[4][NROWS*DD];
__device__ float g_twqkv[LL][DD*384];
__device__ float g_two[LL][DD*DD];
__device__ float g_tw1[LL][DD*FF];
__device__ float g_tw2[LL][FF*DD];
__device__ float g_twout[DD*VV];
__device__ unsigned g_count;
__device__ unsigned g_gen;

struct Params {
    const int* tokens; const float* emb; const float* pos;
    const float* Wq; const float* bq; const float* Wk; const float* bk;
    const float* Wv; const float* bv; const float* Wo; const float* bo;
    const float* W1; const float* b1; const float* W2; const float* b2;
    const float* g1; const float* be1; const float* g2; const float* be2;
    const float* Wout; const float* bout;
    float* out;
};

// ---------------- l_mul elementwise transform ----------------
// e = floor(log2|x|)+1; f(x) = round(x*2^-e * 8) * 2^(2e-3); lmul term == f(x)*f(w)
__device__ __forceinline__ float lmul_f(float x) {
    float ax = fabsf(x);
    if (ax == 0.0f) return 0.0f;
    int e = (int)floorf(log2f(ax)) + 1;
    if (e < -60 || e > 60) {
        float m = ldexpf(x, -e);
        float r = rintf(m * 8.0f);
        return ldexpf(r, 2*e - 3);
    }
    float m = x * __int_as_float((unsigned)(127 - e) << 23);
    float r = rintf(m * 8.0f);
    return r * __int_as_float((unsigned)((2*e - 3) + 127) << 23);
}

// ---------------- grid barrier ----------------
__device__ __forceinline__ void gbar() {
    __syncthreads();
    if (threadIdx.x == 0) {
        __threadfence();
        unsigned gen = *((volatile unsigned*)&g_gen);
        if (atomicAdd(&g_count, 1u) == NB - 1u) {
            atomicExch(&g_count, 0u);
            __threadfence();
            atomicExch(&g_gen, gen + 1u);
        } else {
            while (*((volatile unsigned*)&g_gen) == gen) __nanosleep(32);
        }
        __threadfence();
    }
    __syncthreads();
}

// ---------------- phase 0: weight transform + embed ----------------
__device__ void transform_all(const Params* __restrict__ P) {
    const int t0 = blockIdx.x * NT + threadIdx.x;
    const int STEP = NB * NT;
    for (int i = t0; i < LL*DD*384; i += STEP) {
        int l = i / (DD*384); int r = i - l*(DD*384);
        int k = r / 384, n = r - k*384;
        const float* src; int nn;
        if (n < 128)      { src = P->Wq + l*DD*DD; nn = n; }
        else if (n < 256) { src = P->Wk + l*DD*DD; nn = n - 128; }
        else              { src = P->Wv + l*DD*DD; nn = n - 256; }
        g_twqkv[l][k*384 + n] = lmul_f(src[nn*DD + k]);
    }
    for (int i = t0; i < LL*DD*DD; i += STEP) {
        int l = i / (DD*DD); int r = i - l*(DD*DD);
        int k = r >> 7, n = r & 127;
        g_two[l][k*DD + n] = lmul_f(P->Wo[l*DD*DD + n*DD + k]);
    }
    for (int i = t0; i < LL*DD*FF; i += STEP) {
        int l = i / (DD*FF); int r = i - l*(DD*FF);
        int k = r >> 9, n = r & 511;
        g_tw1[l][k*FF + n] = lmul_f(P->W1[l*FF*DD + n*DD + k]);
    }
    for (int i = t0; i < LL*FF*DD; i += STEP) {
        int l = i / (FF*DD); int r = i - l*(FF*DD);
        int k = r >> 7, n = r & 127;
        g_tw2[l][k*DD + n] = lmul_f(P->W2[l*DD*FF + n*FF + k]);
    }
    for (int i = t0; i < DD*VV; i += STEP) {
        int k = i >> 10, n = i & 1023;
        g_twout[k*VV + n] = lmul_f(P->Wout[n*DD + k]);
    }
    for (int i = t0; i < NROWS*DD; i += STEP) {
        int row = i >> 7, d = i & 127;
        int s = row & (BBS - 1);
        g_x[i] = P->emb[P->tokens[row]*DD + d] + P->pos[s*DD + d];
    }
}

// ---------------- GEMM tile: (RPT*4) rows x 64 cols, K-chunk = 128 -----------
// 256 threads: c = tid&63 (col), g = tid>>6 (0..3) -> rows g*RPT..g*RPT+RPT-1
template<int RPT>
__device__ __forceinline__ void gemm_tile64(
    const float* __restrict__ X, int ldx, int kbeg,
    const float* __restrict__ W, int N,
    const float* __restrict__ bias,    // indexed [c]; may be null
    int relu,
    float* __restrict__ Y, int ldy,
    int row0, int col0, float* __restrict__ xs /* ROWS*132 */)
{
    const int ROWS = RPT * 4;
    const int tid = threadIdx.x;
    #pragma unroll
    for (int i = 0; i < ROWS*128/NT; ++i) {
        int idx = tid + i*NT;
        int r = idx >> 7, k = idx & 127;
        xs[r*132 + k] = lmul_f(X[(row0 + r)*ldx + kbeg + k]);
    }
    __syncthreads();
    const int c = tid & 63;
    const int g = tid >> 6;
    const float* wp = W + (size_t)kbeg * N + col0 + c;
    const float* xp[RPT];
    #pragma unroll
    for (int j = 0; j < RPT; ++j) xp[j] = xs + (g*RPT + j)*132;
    float acc[RPT];
    #pragma unroll
    for (int j = 0; j < RPT; ++j) acc[j] = 0.f;
    #pragma unroll 8
    for (int k = 0; k < 128; k += 4) {
        float w0 = wp[(size_t)(k+0)*N];
        float w1 = wp[(size_t)(k+1)*N];
        float w2 = wp[(size_t)(k+2)*N];
        float w3 = wp[(size_t)(k+3)*N];
        #pragma unroll
        for (int j = 0; j < RPT; ++j) {
            float4 v = *(const float4*)(xp[j] + k);
            acc[j] = fmaf(v.x, w0, acc[j]);
            acc[j] = fmaf(v.y, w1, acc[j]);
            acc[j] = fmaf(v.z, w2, acc[j]);
            acc[j] = fmaf(v.w, w3, acc[j]);
        }
    }
    float b = bias ? bias[c] : 0.f;
    #pragma unroll
    for (int j = 0; j < RPT; ++j) {
        float a = acc[j] + b;
        if (relu) a = fmaxf(a, 0.f);
        Y[(size_t)(row0 + g*RPT + j)*ldy + col0 + c] = a;
    }
    __syncthreads();
}

// ---------------- attention tile: (b, h, 4-query block) ----------------------
__device__ void attn_tile(
    const float* __restrict__ qkv, float* __restrict__ attout,
    int b, int h, int qb, float* __restrict__ sm)
{
    float* ksh = sm;               // 128*33 = 4224
    float* vsh = sm + 4224;        // 128*33
    float* qsh = sm + 8448;        // 4*32 = 128
    float* psh = sm + 8576;        // 4*128 = 512
    const int tid = threadIdx.x;
    #pragma unroll
    for (int i = 0; i < 16; ++i) {
        int idx = tid + i*NT;       // 0..4095
        int j = idx >> 5, d = idx & 31;
        const float* base = qkv + (size_t)(b*BBS + j)*384 + h*DK + d;
        ksh[j*33 + d] = base[128];
        vsh[j*33 + d] = base[256];
    }
    if (tid < 128) {
        int qi = tid >> 5, d = tid & 31;
        qsh[tid] = qkv[(size_t)(b*BBS + qb*4 + qi)*384 + h*DK + d];
    }
    __syncthreads();
    const int wid = tid >> 5, lane = tid & 31;
    if (wid < 4) {
        const int q = qb*4 + wid;
        float qr[32];
        #pragma unroll
        for (int d = 0; d < 32; d += 4) {
            float4 t = *(const float4*)(qsh + wid*32 + d);
            qr[d] = t.x; qr[d+1] = t.y; qr[d+2] = t.z; qr[d+3] = t.w;
        }
        const float* k0 = ksh + (lane     )*33;
        const float* k1 = ksh + (lane + 32)*33;
        const float* k2 = ksh + (lane + 64)*33;
        const float* k3 = ksh + (lane + 96)*33;
        float s0 = 0.f, s1 = 0.f, s2 = 0.f, s3 = 0.f;
        #pragma unroll
        for (int d = 0; d < 32; ++d) {
            float qd = qr[d];
            s0 = fmaf(qd, k0[d], s0);
            s1 = fmaf(qd, k1[d], s1);
            s2 = fmaf(qd, k2[d], s2);
            s3 = fmaf(qd, k3[d], s3);
        }
        const float scale = 0.17677669529663687f;  // 1/sqrt(32)
        s0 *= scale; s1 *= scale; s2 *= scale; s3 *= scale;
        float m = fmaxf(fmaxf(s0, s1), fmaxf(s2, s3));
        #pragma unroll
        for (int o = 16; o; o >>= 1) m = fmaxf(m, __shfl_xor_sync(0xffffffffu, m, o));
        float p0 = __expf(s0 - m), p1 = __expf(s1 - m), p2 = __expf(s2 - m), p3 = __expf(s3 - m);
        float lsum = p0 + p1 + p2 + p3;
        #pragma unroll
        for (int o = 16; o; o >>= 1) lsum += __shfl_xor_sync(0xffffffffu, lsum, o);
        float* pp = psh + wid*128;
        pp[lane     ] = p0;
        pp[lane + 32] = p1;
        pp[lane + 64] = p2;
        pp[lane + 96] = p3;
        __syncwarp();
        float o0 = 0.f, o1 = 0.f, o2 = 0.f, o3 = 0.f;
        #pragma unroll 8
        for (int j = 0; j < 128; j += 4) {
            o0 = fmaf(pp[j+0], vsh[(j+0)*33 + lane], o0);
            o1 = fmaf(pp[j+1], vsh[(j+1)*33 + lane], o1);
            o2 = fmaf(pp[j+2], vsh[(j+2)*33 + lane], o2);
            o3 = fmaf(pp[j+3], vsh[(j+3)*33 + lane], o3);
        }
        attout[(size_t)(b*BBS + q)*DD + h*DK + lane] = ((o0 + o1) + (o2 + o3)) / lsum;
    }
    __syncthreads();
}

// ---------------- O-proj + residual + LN1 (4 rows/block, 64 blocks) ----------
__device__ void oproj_ln(
    const float* __restrict__ att, const float* __restrict__ W,
    const float* __restrict__ bo, const float* __restrict__ g1,
    const float* __restrict__ be1, float* __restrict__ x,
    float* __restrict__ sm)
{
    if (blockIdx.x >= 64) return;
    const int row0 = blockIdx.x * 4;
    float* as   = sm;          // 4*132
    float* vals = sm + 544;    // 4*132
    float* st   = sm + 1088;   // 8
    const int tid = threadIdx.x;
    #pragma unroll
    for (int i = 0; i < 2; ++i) {
        int idx = tid + i*NT;          // 0..511
        int r = idx >> 7, k = idx & 127;
        as[r*132 + k] = lmul_f(att[(row0 + r)*DD + k]);
    }
    __syncthreads();
    const int c = tid & 127, rg = tid >> 7;       // rows rg*2, rg*2+1
    const float* x0p = as + (rg*2    )*132;
    const float* x1p = as + (rg*2 + 1)*132;
    const float* wp = W + c;
    float a0 = 0.f, a1 = 0.f;
    #pragma unroll 8
    for (int k = 0; k < 128; k += 4) {
        float4 v0 = *(const float4*)(x0p + k);
        float4 v1 = *(const float4*)(x1p + k);
        float w0 = wp[(k+0)*DD], w1 = wp[(k+1)*DD], w2 = wp[(k+2)*DD], w3 = wp[(k+3)*DD];
        a0 = fmaf(v0.x, w0, a0); a1 = fmaf(v1.x, w0, a1);
        a0 = fmaf(v0.y, w1, a0); a1 = fmaf(v1.y, w1, a1);
        a0 = fmaf(v0.z, w2, a0); a1 = fmaf(v1.z, w2, a1);
        a0 = fmaf(v0.w, w3, a0); a1 = fmaf(v1.w, w3, a1);
    }
    float b = bo[c];
    const int r0 = row0 + rg*2, r1 = r0 + 1;
    float v0 = x[r0*DD + c] + a0 + b;
    float v1 = x[r1*DD + c] + a1 + b;
    vals[(rg*2    )*132 + c] = v0;
    vals[(rg*2 + 1)*132 + c] = v1;
    __syncthreads();
    const int wid = tid >> 5, lane = tid & 31;
    if (wid < 4) {
        float s = 0.f, sq = 0.f;
        #pragma unroll
        for (int i = 0; i < 4; ++i) {
            float v = vals[wid*132 + lane + i*32];
            s += v; sq = fmaf(v, v, sq);
        }
        #pragma unroll
        for (int o = 16; o; o >>= 1) {
            s  += __shfl_xor_sync(0xffffffffu, s, o);
            sq += __shfl_xor_sync(0xffffffffu, sq, o);
        }
        if (lane == 0) {
            float mean = s * (1.f/128.f);
            float var  = sq * (1.f/128.f) - mean*mean;
            st[wid*2]     = mean;
            st[wid*2 + 1] = rsqrtf(var + 1e-5f);
        }
    }
    __syncthreads();
    {
        float gm = g1[c], bb = be1[c];
        float m0 = st[(rg*2)*2],     rs0 = st[(rg*2)*2 + 1];
        float m1 = st[(rg*2+1)*2],   rs1 = st[(rg*2+1)*2 + 1];
        x[r0*DD + c] = (v0 - m0)*rs0*gm + bb;
        x[r1*DD + c] = (v1 - m1)*rs1*gm + bb;
    }
    __syncthreads();
}

// ---------------- FF2 partial combine + bias + residual + LN2 -----------------
__device__ void ff2_ln(
    const float* __restrict__ b2, const float* __restrict__ g2,
    const float* __restrict__ be2, float* __restrict__ x,
    float* __restrict__ sm)
{
    if (blockIdx.x >= 128) return;
    float* vals = sm;         // 2*132
    float* st   = sm + 272;   // 4
    const int tid = threadIdx.x;
    const int c = tid & 127, rg = tid >> 7;
    const int row = blockIdx.x*2 + rg;
    float v = x[row*DD + c] + b2[c];
    #pragma unroll
    for (int ks = 0; ks < 4; ++ks) v += g_ffp[ks][row*DD + c];
    vals[rg*132 + c] = v;
    __syncthreads();
    const int wid = tid >> 5, lane = tid & 31;
    if (wid < 2) {
        float s = 0.f, sq = 0.f;
        #pragma unroll
        for (int i = 0; i < 4; ++i) {
            float t = vals[wid*132 + lane + i*32];
            s += t; sq = fmaf(t, t, sq);
        }
        #pragma unroll
        for (int o = 16; o; o >>= 1) {
            s  += __shfl_xor_sync(0xffffffffu, s, o);
            sq += __shfl_xor_sync(0xffffffffu, sq, o);
        }
        if (lane == 0) {
            float mean = s * (1.f/128.f);
            float var  = sq * (1.f/128.f) - mean*mean;
            st[wid*2]     = mean;
            st[wid*2 + 1] = rsqrtf(var + 1e-5f);
        }
    }
    __syncthreads();
    x[row*DD + c] = (v - st[rg*2])*st[rg*2 + 1]*g2[c] + be2[c];
    __syncthreads();
}

// ---------------- the one persistent kernel ----------------
__global__ void __launch_bounds__(NT, 2) model_kernel(Params P) {
    __shared__ __align__(16) float sm[9216];

    // P0: weight transforms + embedding
    transform_all(&P);
    gbar();

    for (int l = 0; l < LL; ++l) {
        // P1: QKV fused GEMM — 192 tiles (32 row x 6 col64)
        if (blockIdx.x < 192) {
            int rt = blockIdx.x & 31, ct = blockIdx.x >> 5;     // ct 0..5
            int col0 = ct * 64;
            int seg = col0 >> 7;                                // 0..2
            const float* segb = (seg == 0 ? P.bq : seg == 1 ? P.bk : P.bv)
                                + l*DD + (col0 & 127);
            gemm_tile64<2>(g_x, DD, 0, g_twqkv[l], 384, segb, 0,
                           g_qkv, 384, rt*8, col0, sm);
        }
        gbar();

        // P2: attention — 256 tiles (b, h, 4-query block)
        if (blockIdx.x < 256) {
            int b = blockIdx.x >> 7, h = (blockIdx.x >> 5) & 3, qb = blockIdx.x & 31;
            attn_tile(g_qkv, g_att, b, h, qb, sm);
        }
        gbar();

        // P3: O-proj + residual + LN1 — 64 blocks
        oproj_ln(g_att, g_two[l], P.bo + l*DD, P.g1 + l*DD, P.be1 + l*DD, g_x, sm);
        gbar();

        // P4: FF1 + relu — 256 tiles (32 row x 8 col64)
        if (blockIdx.x < 256) {
            int rt = blockIdx.x & 31, ct = blockIdx.x >> 5;     // ct 0..7
            gemm_tile64<2>(g_x, DD, 0, g_tw1[l], FF, P.b1 + l*FF + ct*64, 1,
                           g_ff, FF, rt*8, ct*64, sm);
        }
        gbar();

        // P5: FF2 k-split partials — 256 tiles (32 row x 2 col64 x 4 k-chunks)
        if (blockIdx.x < 256) {
            int rt = blockIdx.x & 31, ct = (blockIdx.x >> 5) & 1, kc = blockIdx.x >> 6;
            gemm_tile64<2>(g_ff, FF, kc*128, g_tw2[l], DD, (const float*)0, 0,
                           g_ffp[kc], DD, rt*8, ct*64, sm);
        }
        gbar();

        // P6: partial sum + bias + residual + LN2 — 128 blocks
        ff2_ln(P.b2 + l*DD, P.g2 + l*DD, P.be2 + l*DD, g_x, sm);
        gbar();
    }

    // P7: final vocab projection — 256 tiles (16 rowtiles(16r) x 16 col64)
    if (blockIdx.x < 256) {
        int rt = blockIdx.x & 15, ct = blockIdx.x >> 4;
        gemm_tile64<4>(g_x, DD, 0, g_twout, VV, P.bout + ct*64, 0,
                       P.out, VV, rt*16, ct*64, sm);
    }
}

extern "C" void kernel_launch(void* const* d_in, const int* in_sizes, int n_in,
                              void* d_out, int out_size) {
    Params P;
    P.tokens = (const int*)  d_in[0];
    P.emb    = (const float*)d_in[1];
    P.pos    = (const float*)d_in[2];
    P.Wq     = (const float*)d_in[3];
    P.bq     = (const float*)d_in[4];
    P.Wk     = (const float*)d_in[5];
    P.bk     = (const float*)d_in[6];
    P.Wv     = (const float*)d_in[7];
    P.bv     = (const float*)d_in[8];
    P.Wo     = (const float*)d_in[9];
    P.bo     = (const float*)d_in[10];
    P.W1     = (const float*)d_in[11];
    P.b1     = (const float*)d_in[12];
    P.W2     = (const float*)d_in[13];
    P.b2     = (const float*)d_in[14];
    P.g1     = (const float*)d_in[15];
    P.be1    = (const float*)d_in[16];
    P.g2     = (const float*)d_in[17];
    P.be2    = (const float*)d_in[18];
    P.Wout   = (const float*)d_in[19];
    P.bout   = (const float*)d_in[20];
    P.out    = (float*)d_out;

    model_kernel<<<NB, NT>>>(P);
}

// round 7
// speedup vs baseline: 1.4674x; 1.1410x over previous
#include <cuda_runtime.h>
#include <math.h>

#define NB 296
#define NT 256
#define NROWS 256      // B*S
#define BBS 128        // S
#define DD 128
#define FF 512
#define VV 1024
#define DK 32
#define LL 2

// ---------------- device scratch ----------------
__device__ float g_x[NROWS*DD];
__device__ float g_qkv[NROWS*384];
__device__ float g_att[NROWS*DD];
__device__ float g_ff[NROWS*FF];
__device__ float g_ffp[4][NROWS*DD];
__device__ float g_twqkv[LL][DD*384];
__device__ float g_two[LL][DD*DD];
__device__ float g_tw1[LL][DD*FF];
__device__ float g_tw2[LL][FF*DD];
__device__ float g_twout[DD*VV];
__device__ unsigned g_count;
__device__ unsigned g_gen;

struct Params {
    const int* tokens; const float* emb; const float* pos;
    const float* Wq; const float* bq; const float* Wk; const float* bk;
    const float* Wv; const float* bv; const float* Wo; const float* bo;
    const float* W1; const float* b1; const float* W2; const float* b2;
    const float* g1; const float* be1; const float* g2; const float* be2;
    const float* Wout; const float* bout;
    float* out;
};

// ---------------- l_mul elementwise transform (bit-twiddled) ----------------
// Reference: e = floor(log2|x|)+1; m = x*2^-e; r = round(m*8); f = r*2^(2e-3).
// For normal floats floor(log2|x|) = rawexp-127 exactly, so e = rawexp-126.
// Denormals/zero -> 0 (their contribution is ~2^-250, far below tolerance).
__device__ __forceinline__ float lmul_f(float x) {
    unsigned bits = __float_as_uint(x);
    int expo = (int)((bits >> 23) & 0xffu);
    if (expo == 0) return 0.0f;                 // zero or denormal
    int e = expo - 126;                         // floor(log2|x|)+1
    if (e < -40) return 0.0f;                   // negligible magnitude
    // m = x * 2^-e exactly: keep sign+mantissa, set exponent field to 126 (=2^-1)
    float m = __int_as_float((bits & 0x807fffffu) | (126u << 23));
    float r = rintf(m * 8.0f);                  // round-half-even, matches jnp.round
    return r * __int_as_float((unsigned)(2*e - 3 + 127) << 23);  // exact 2^(2e-3)
}

// ---------------- grid barrier ----------------
__device__ __forceinline__ void gbar() {
    __syncthreads();
    if (threadIdx.x == 0) {
        __threadfence();
        unsigned gen = *((volatile unsigned*)&g_gen);
        if (atomicAdd(&g_count, 1u) == NB - 1u) {
            atomicExch(&g_count, 0u);
            __threadfence();
            atomicExch(&g_gen, gen + 1u);
        } else {
            while (*((volatile unsigned*)&g_gen) == gen) __nanosleep(32);
        }
        __threadfence();
    }
    __syncthreads();
}

// ---------------- phase 0: weight transform + embed ----------------
__device__ void transform_all(const Params* __restrict__ P) {
    const int t0 = blockIdx.x * NT + threadIdx.x;
    const int STEP = NB * NT;
    for (int i = t0; i < LL*DD*384; i += STEP) {
        int l = i / (DD*384); int r = i - l*(DD*384);
        int k = r / 384, n = r - k*384;
        const float* src; int nn;
        if (n < 128)      { src = P->Wq + l*DD*DD; nn = n; }
        else if (n < 256) { src = P->Wk + l*DD*DD; nn = n - 128; }
        else              { src = P->Wv + l*DD*DD; nn = n - 256; }
        g_twqkv[l][k*384 + n] = lmul_f(src[nn*DD + k]);
    }
    for (int i = t0; i < LL*DD*DD; i += STEP) {
        int l = i / (DD*DD); int r = i - l*(DD*DD);
        int k = r >> 7, n = r & 127;
        g_two[l][k*DD + n] = lmul_f(P->Wo[l*DD*DD + n*DD + k]);
    }
    for (int i = t0; i < LL*DD*FF; i += STEP) {
        int l = i / (DD*FF); int r = i - l*(DD*FF);
        int k = r >> 9, n = r & 511;
        g_tw1[l][k*FF + n] = lmul_f(P->W1[l*FF*DD + n*DD + k]);
    }
    for (int i = t0; i < LL*FF*DD; i += STEP) {
        int l = i / (FF*DD); int r = i - l*(FF*DD);
        int k = r >> 7, n = r & 127;
        g_tw2[l][k*DD + n] = lmul_f(P->W2[l*DD*FF + n*FF + k]);
    }
    for (int i = t0; i < DD*VV; i += STEP) {
        int k = i >> 10, n = i & 1023;
        g_twout[k*VV + n] = lmul_f(P->Wout[n*DD + k]);
    }
    for (int i = t0; i < NROWS*DD; i += STEP) {
        int row = i >> 7, d = i & 127;
        int s = row & (BBS - 1);
        g_x[i] = P->emb[P->tokens[row]*DD + d] + P->pos[s*DD + d];
    }
}

// ---------------- GEMM tile: (RPT*4) rows x 64 cols, K-chunk = 128 -----------
// 256 threads: c = tid&63 (col), g = tid>>6 (0..3) -> rows g*RPT..g*RPT+RPT-1
// Weight loads batched 32 at a time into registers (MLP=32) then consumed.
template<int RPT>
__device__ __forceinline__ void gemm_tile64(
    const float* __restrict__ X, int ldx, int kbeg,
    const float* __restrict__ W, int N,
    const float* __restrict__ bias,    // indexed [c]; may be null
    int relu,
    float* __restrict__ Y, int ldy,
    int row0, int col0, float* __restrict__ xs /* (RPT*4)*132 */)
{
    const int ROWS = RPT * 4;
    const int tid = threadIdx.x;
    #pragma unroll
    for (int i = 0; i < ROWS*128/NT; ++i) {
        int idx = tid + i*NT;
        int r = idx >> 7, k = idx & 127;
        xs[r*132 + k] = lmul_f(X[(row0 + r)*ldx + kbeg + k]);
    }
    __syncthreads();
    const int c = tid & 63;
    const int g = tid >> 6;
    const float* wp = W + (size_t)kbeg * N + col0 + c;
    const float* xb = xs + g*RPT*132;
    float acc[RPT];
    #pragma unroll
    for (int j = 0; j < RPT; ++j) acc[j] = 0.f;
    #pragma unroll
    for (int kc = 0; kc < 128; kc += 32) {
        float wr[32];
        #pragma unroll
        for (int j = 0; j < 32; ++j) wr[j] = wp[(size_t)(kc + j)*N];
        #pragma unroll
        for (int j = 0; j < 32; j += 4) {
            #pragma unroll
            for (int r = 0; r < RPT; ++r) {
                float4 v = *(const float4*)(xb + r*132 + kc + j);
                acc[r] = fmaf(v.x, wr[j+0], acc[r]);
                acc[r] = fmaf(v.y, wr[j+1], acc[r]);
                acc[r] = fmaf(v.z, wr[j+2], acc[r]);
                acc[r] = fmaf(v.w, wr[j+3], acc[r]);
            }
        }
    }
    float b = bias ? bias[c] : 0.f;
    #pragma unroll
    for (int j = 0; j < RPT; ++j) {
        float a = acc[j] + b;
        if (relu) a = fmaxf(a, 0.f);
        Y[(size_t)(row0 + g*RPT + j)*ldy + col0 + c] = a;
    }
    __syncthreads();
}

// ---------------- attention tile: (b, h, 4-query block) ----------------------
__device__ void attn_tile(
    const float* __restrict__ qkv, float* __restrict__ attout,
    int b, int h, int qb, float* __restrict__ sm)
{
    float* ksh = sm;               // 128*33 = 4224
    float* vsh = sm + 4224;        // 128*33
    float* qsh = sm + 8448;        // 4*32 = 128
    float* psh = sm + 8576;        // 4*128 = 512
    const int tid = threadIdx.x;
    #pragma unroll
    for (int i = 0; i < 16; ++i) {
        int idx = tid + i*NT;       // 0..4095
        int j = idx >> 5, d = idx & 31;
        const float* base = qkv + (size_t)(b*BBS + j)*384 + h*DK + d;
        ksh[j*33 + d] = base[128];
        vsh[j*33 + d] = base[256];
    }
    if (tid < 128) {
        int qi = tid >> 5, d = tid & 31;
        qsh[tid] = qkv[(size_t)(b*BBS + qb*4 + qi)*384 + h*DK + d];
    }
    __syncthreads();
    const int wid = tid >> 5, lane = tid & 31;
    if (wid < 4) {
        const int q = qb*4 + wid;
        float qr[32];
        #pragma unroll
        for (int d = 0; d < 32; d += 4) {
            float4 t = *(const float4*)(qsh + wid*32 + d);
            qr[d] = t.x; qr[d+1] = t.y; qr[d+2] = t.z; qr[d+3] = t.w;
        }
        const float* k0 = ksh + (lane     )*33;
        const float* k1 = ksh + (lane + 32)*33;
        const float* k2 = ksh + (lane + 64)*33;
        const float* k3 = ksh + (lane + 96)*33;
        float s0 = 0.f, s1 = 0.f, s2 = 0.f, s3 = 0.f;
        #pragma unroll
        for (int d = 0; d < 32; ++d) {
            float qd = qr[d];
            s0 = fmaf(qd, k0[d], s0);
            s1 = fmaf(qd, k1[d], s1);
            s2 = fmaf(qd, k2[d], s2);
            s3 = fmaf(qd, k3[d], s3);
        }
        const float scale = 0.17677669529663687f;  // 1/sqrt(32)
        s0 *= scale; s1 *= scale; s2 *= scale; s3 *= scale;
        float m = fmaxf(fmaxf(s0, s1), fmaxf(s2, s3));
        #pragma unroll
        for (int o = 16; o; o >>= 1) m = fmaxf(m, __shfl_xor_sync(0xffffffffu, m, o));
        float p0 = __expf(s0 - m), p1 = __expf(s1 - m), p2 = __expf(s2 - m), p3 = __expf(s3 - m);
        float lsum = p0 + p1 + p2 + p3;
        #pragma unroll
        for (int o = 16; o; o >>= 1) lsum += __shfl_xor_sync(0xffffffffu, lsum, o);
        float* pp = psh + wid*128;
        pp[lane     ] = p0;
        pp[lane + 32] = p1;
        pp[lane + 64] = p2;
        pp[lane + 96] = p3;
        __syncwarp();
        float o0 = 0.f, o1 = 0.f, o2 = 0.f, o3 = 0.f;
        #pragma unroll 8
        for (int j = 0; j < 128; j += 4) {
            o0 = fmaf(pp[j+0], vsh[(j+0)*33 + lane], o0);
            o1 = fmaf(pp[j+1], vsh[(j+1)*33 + lane], o1);
            o2 = fmaf(pp[j+2], vsh[(j+2)*33 + lane], o2);
            o3 = fmaf(pp[j+3], vsh[(j+3)*33 + lane], o3);
        }
        attout[(size_t)(b*BBS + q)*DD + h*DK + lane] = ((o0 + o1) + (o2 + o3)) / lsum;
    }
    __syncthreads();
}

// ---------------- O-proj + residual + LN1 (4 rows/block, 64 blocks) ----------
__device__ void oproj_ln(
    const float* __restrict__ att, const float* __restrict__ W,
    const float* __restrict__ bo, const float* __restrict__ g1,
    const float* __restrict__ be1, float* __restrict__ x,
    float* __restrict__ sm)
{
    if (blockIdx.x >= 64) return;
    const int row0 = blockIdx.x * 4;
    float* as   = sm;          // 4*132
    float* vals = sm + 544;    // 4*132
    float* st   = sm + 1088;   // 8
    const int tid = threadIdx.x;
    #pragma unroll
    for (int i = 0; i < 2; ++i) {
        int idx = tid + i*NT;          // 0..511
        int r = idx >> 7, k = idx & 127;
        as[r*132 + k] = lmul_f(att[(row0 + r)*DD + k]);
    }
    __syncthreads();
    const int c = tid & 127, rg = tid >> 7;       // rows rg*2, rg*2+1
    const float* x0p = as + (rg*2    )*132;
    const float* x1p = as + (rg*2 + 1)*132;
    const float* wp = W + c;
    float a0 = 0.f, a1 = 0.f;
    #pragma unroll
    for (int kc = 0; kc < 128; kc += 32) {
        float wr[32];
        #pragma unroll
        for (int j = 0; j < 32; ++j) wr[j] = wp[(kc + j)*DD];
        #pragma unroll
        for (int j = 0; j < 32; j += 4) {
            float4 v0 = *(const float4*)(x0p + kc + j);
            float4 v1 = *(const float4*)(x1p + kc + j);
            a0 = fmaf(v0.x, wr[j+0], a0); a1 = fmaf(v1.x, wr[j+0], a1);
            a0 = fmaf(v0.y, wr[j+1], a0); a1 = fmaf(v1.y, wr[j+1], a1);
            a0 = fmaf(v0.z, wr[j+2], a0); a1 = fmaf(v1.z, wr[j+2], a1);
            a0 = fmaf(v0.w, wr[j+3], a0); a1 = fmaf(v1.w, wr[j+3], a1);
        }
    }
    float b = bo[c];
    const int r0 = row0 + rg*2, r1 = r0 + 1;
    float v0 = x[r0*DD + c] + a0 + b;
    float v1 = x[r1*DD + c] + a1 + b;
    vals[(rg*2    )*132 + c] = v0;
    vals[(rg*2 + 1)*132 + c] = v1;
    __syncthreads();
    const int wid = tid >> 5, lane = tid & 31;
    if (wid < 4) {
        float s = 0.f, sq = 0.f;
        #pragma unroll
        for (int i = 0; i < 4; ++i) {
            float v = vals[wid*132 + lane + i*32];
            s += v; sq = fmaf(v, v, sq);
        }
        #pragma unroll
        for (int o = 16; o; o >>= 1) {
            s  += __shfl_xor_sync(0xffffffffu, s, o);
            sq += __shfl_xor_sync(0xffffffffu, sq, o);
        }
        if (lane == 0) {
            float mean = s * (1.f/128.f);
            float var  = sq * (1.f/128.f) - mean*mean;
            st[wid*2]     = mean;
            st[wid*2 + 1] = rsqrtf(var + 1e-5f);
        }
    }
    __syncthreads();
    {
        float gm = g1[c], bb = be1[c];
        float m0 = st[(rg*2)*2],     rs0 = st[(rg*2)*2 + 1];
        float m1 = st[(rg*2+1)*2],   rs1 = st[(rg*2+1)*2 + 1];
        x[r0*DD + c] = (v0 - m0)*rs0*gm + bb;
        x[r1*DD + c] = (v1 - m1)*rs1*gm + bb;
    }
    __syncthreads();
}

// ---------------- FF2 partial combine + bias + residual + LN2 -----------------
__device__ void ff2_ln(
    const float* __restrict__ b2, const float* __restrict__ g2,
    const float* __restrict__ be2, float* __restrict__ x,
    float* __restrict__ sm)
{
    if (blockIdx.x >= 128) return;
    float* vals = sm;         // 2*132
    float* st   = sm + 272;   // 4
    const int tid = threadIdx.x;
    const int c = tid & 127, rg = tid >> 7;
    const int row = blockIdx.x*2 + rg;
    float v = x[row*DD + c] + b2[c];
    #pragma unroll
    for (int ks = 0; ks < 4; ++ks) v += g_ffp[ks][row*DD + c];
    vals[rg*132 + c] = v;
    __syncthreads();
    const int wid = tid >> 5, lane = tid & 31;
    if (wid < 2) {
        float s = 0.f, sq = 0.f;
        #pragma unroll
        for (int i = 0; i < 4; ++i) {
            float t = vals[wid*132 + lane + i*32];
            s += t; sq = fmaf(t, t, sq);
        }
        #pragma unroll
        for (int o = 16; o; o >>= 1) {
            s  += __shfl_xor_sync(0xffffffffu, s, o);
            sq += __shfl_xor_sync(0xffffffffu, sq, o);
        }
        if (lane == 0) {
            float mean = s * (1.f/128.f);
            float var  = sq * (1.f/128.f) - mean*mean;
            st[wid*2]     = mean;
            st[wid*2 + 1] = rsqrtf(var + 1e-5f);
        }
    }
    __syncthreads();
    x[row*DD + c] = (v - st[rg*2])*st[rg*2 + 1]*g2[c] + be2[c];
    __syncthreads();
}

// ---------------- the one persistent kernel ----------------
__global__ void __launch_bounds__(NT, 2) model_kernel(Params P) {
    __shared__ __align__(16) float sm[9216];

    // P0: weight transforms + embedding
    transform_all(&P);
    gbar();

    for (int l = 0; l < LL; ++l) {
        // P1: QKV fused GEMM — 96 tiles (16 rowtiles(16r) x 6 col64)
        if (blockIdx.x < 96) {
            int rt = blockIdx.x & 15, ct = blockIdx.x >> 4;     // ct 0..5
            int col0 = ct * 64;
            int seg = col0 >> 7;                                // 0..2
            const float* segb = (seg == 0 ? P.bq : seg == 1 ? P.bk : P.bv)
                                + l*DD + (col0 & 127);
            gemm_tile64<4>(g_x, DD, 0, g_twqkv[l], 384, segb, 0,
                           g_qkv, 384, rt*16, col0, sm);
        }
        gbar();

        // P2: attention — 256 tiles (b, h, 4-query block)
        if (blockIdx.x < 256) {
            int b = blockIdx.x >> 7, h = (blockIdx.x >> 5) & 3, qb = blockIdx.x & 31;
            attn_tile(g_qkv, g_att, b, h, qb, sm);
        }
        gbar();

        // P3: O-proj + residual + LN1 — 64 blocks
        oproj_ln(g_att, g_two[l], P.bo + l*DD, P.g1 + l*DD, P.be1 + l*DD, g_x, sm);
        gbar();

        // P4: FF1 + relu — 128 tiles (16 rowtiles(16r) x 8 col64)
        if (blockIdx.x < 128) {
            int rt = blockIdx.x & 15, ct = blockIdx.x >> 4;     // ct 0..7
            gemm_tile64<4>(g_x, DD, 0, g_tw1[l], FF, P.b1 + l*FF + ct*64, 1,
                           g_ff, FF, rt*16, ct*64, sm);
        }
        gbar();

        // P5: FF2 k-split partials — 128 tiles (16 rt x 2 col64 x 4 k-chunks)
        if (blockIdx.x < 128) {
            int rt = blockIdx.x & 15, ct = (blockIdx.x >> 4) & 1, kc = blockIdx.x >> 5;
            gemm_tile64<4>(g_ff, FF, kc*128, g_tw2[l], DD, (const float*)0, 0,
                           g_ffp[kc], DD, rt*16, ct*64, sm);
        }
        gbar();

        // P6: partial sum + bias + residual + LN2 — 128 blocks
        ff2_ln(P.b2 + l*DD, P.g2 + l*DD, P.be2 + l*DD, g_x, sm);
        gbar();
    }

    // P7: final vocab projection — 128 tiles (8 rowtiles(32r) x 16 col64)
    if (blockIdx.x < 128) {
        int rt = blockIdx.x & 7, ct = blockIdx.x >> 3;
        gemm_tile64<8>(g_x, DD, 0, g_twout, VV, P.bout + ct*64, 0,
                       P.out, VV, rt*32, ct*64, sm);
    }
}

extern "C" void kernel_launch(void* const* d_in, const int* in_sizes, int n_in,
                              void* d_out, int out_size) {
    Params P;
    P.tokens = (const int*)  d_in[0];
    P.emb    = (const float*)d_in[1];
    P.pos    = (const float*)d_in[2];
    P.Wq     = (const float*)d_in[3];
    P.bq     = (const float*)d_in[4];
    P.Wk     = (const float*)d_in[5];
    P.bk     = (const float*)d_in[6];
    P.Wv     = (const float*)d_in[7];
    P.bv     = (const float*)d_in[8];
    P.Wo     = (const float*)d_in[9];
    P.bo     = (const float*)d_in[10];
    P.W1     = (const float*)d_in[11];
    P.b1     = (const float*)d_in[12];
    P.W2     = (const float*)d_in[13];
    P.b2     = (const float*)d_in[14];
    P.g1     = (const float*)d_in[15];
    P.be1    = (const float*)d_in[16];
    P.g2     = (const float*)d_in[17];
    P.be2    = (const float*)d_in[18];
    P.Wout   = (const float*)d_in[19];
    P.bout   = (const float*)d_in[20];
    P.out    = (float*)d_out;

    model_kernel<<<NB, NT>>>(P);
}